// round 2
// baseline (speedup 1.0000x reference)
#include <cuda_runtime.h>
#include <mma.h>

using namespace nvcuda;

#define BATCH 4
#define SEQ_N 4096
#define SEQ_M 4096
#define DIM   512
#define ROWS  (BATCH * SEQ_N)      /* 16384 */
#define ATTN_SCALE 0.125f          /* 64^-0.5 */
#define LN_EPS 1e-5f

/* ---------------- scratch (no allocations allowed) ---------------- */
__device__ float g_q [(size_t)ROWS * DIM];           /*  32 MB */
__device__ float g_kv[(size_t)ROWS * 2 * DIM];       /*  64 MB (k | v) */
__device__ float g_S [(size_t)BATCH * SEQ_N * SEQ_M];/* 256 MB logits/probs */
__device__ float g_O [(size_t)ROWS * DIM];           /*  32 MB attn out */

/* ---------------- tf32x3 WMMA GEMM ----------------
 * C[M,N] = alpha * A[M,K] @ B[K,N], fp32 in/out, near-fp32 accuracy via
 * the 3M tf32 split: a = ah + al, b = bh + bl (tf32 hi + tf32 residual),
 * D += ah*bh + al*bh + ah*bl.
 * A row-major. B row-major if !B_COL; if B_COL, B is [N,K] row-major
 * (used for q @ k^T). Batched via gridDim.z with element strides.
 * Block tile 128x128x32, 8 warps, each warp 64x32 via m16n16k8 frags.
 */
#define BM 128
#define BN 128
#define BK 32
#define APAD 8
#define BPAD 8

template<bool B_COL>
__global__ __launch_bounds__(256) void gemm_tf32x3(
    const float* __restrict__ A, const float* __restrict__ B, float* __restrict__ C,
    int M, int N, int K, int lda, int ldb, int ldc,
    long long sA, long long sB, long long sC, float alpha)
{
    __shared__ float As[BM][BK + APAD];
    __shared__ float Bs[BK][BN + BPAD];

    A += (long long)blockIdx.z * sA;
    B += (long long)blockIdx.z * sB;
    C += (long long)blockIdx.z * sC;

    const int n0  = blockIdx.x * BN;
    const int m0  = blockIdx.y * BM;
    const int tid = threadIdx.x;
    const int warp = tid >> 5;
    const int wm = warp >> 2;   /* 0..1 : 64-row slab */
    const int wn = warp & 3;    /* 0..3 : 32-col slab */

    wmma::fragment<wmma::accumulator, 16, 16, 8, float> acc[4][2];
    #pragma unroll
    for (int i = 0; i < 4; i++)
        #pragma unroll
        for (int j = 0; j < 2; j++)
            wmma::fill_fragment(acc[i][j], 0.0f);

    for (int k0 = 0; k0 < K; k0 += BK) {
        /* ---- stage A tile: 128x32, float4, coalesced ---- */
        #pragma unroll
        for (int i = 0; i < 4; i++) {
            int idx = i * 256 + tid;
            int r   = idx >> 3;
            int c4  = idx & 7;
            float4 v = *reinterpret_cast<const float4*>(
                &A[(size_t)(m0 + r) * lda + k0 + c4 * 4]);
            *reinterpret_cast<float4*>(&As[r][c4 * 4]) = v;
        }
        /* ---- stage B tile: 32x128 ---- */
        if (!B_COL) {
            #pragma unroll
            for (int i = 0; i < 4; i++) {
                int idx = i * 256 + tid;
                int r   = idx >> 5;
                int c4  = idx & 31;
                float4 v = *reinterpret_cast<const float4*>(
                    &B[(size_t)(k0 + r) * ldb + n0 + c4 * 4]);
                *reinterpret_cast<float4*>(&Bs[r][c4 * 4]) = v;
            }
        } else {
            #pragma unroll
            for (int i = 0; i < 4; i++) {
                int idx = i * 256 + tid;
                int n   = idx >> 3;
                int k4  = idx & 7;
                float4 v = *reinterpret_cast<const float4*>(
                    &B[(size_t)(n0 + n) * ldb + k0 + k4 * 4]);
                Bs[k4 * 4 + 0][n] = v.x;
                Bs[k4 * 4 + 1][n] = v.y;
                Bs[k4 * 4 + 2][n] = v.z;
                Bs[k4 * 4 + 3][n] = v.w;
            }
        }
        __syncthreads();

        /* ---- compute: 4 k-steps of 8, tf32x3 ---- */
        #pragma unroll
        for (int kk = 0; kk < BK; kk += 8) {
            wmma::fragment<wmma::matrix_a, 16, 16, 8, wmma::precision::tf32, wmma::row_major> ah[4], al[4];
            wmma::fragment<wmma::matrix_b, 16, 16, 8, wmma::precision::tf32, wmma::row_major> bh[2], bl[2];
            #pragma unroll
            for (int i = 0; i < 4; i++) {
                wmma::load_matrix_sync(ah[i], &As[wm * 64 + i * 16][kk], BK + APAD);
                #pragma unroll
                for (int t = 0; t < ah[i].num_elements; t++) {
                    float orig = ah[i].x[t];
                    float h = wmma::__float_to_tf32(orig);
                    ah[i].x[t] = h;
                    al[i].x[t] = wmma::__float_to_tf32(orig - h);
                }
            }
            #pragma unroll
            for (int j = 0; j < 2; j++) {
                wmma::load_matrix_sync(bh[j], &Bs[kk][wn * 32 + j * 16], BN + BPAD);
                #pragma unroll
                for (int t = 0; t < bh[j].num_elements; t++) {
                    float orig = bh[j].x[t];
                    float h = wmma::__float_to_tf32(orig);
                    bh[j].x[t] = h;
                    bl[j].x[t] = wmma::__float_to_tf32(orig - h);
                }
            }
            /* small terms first, then the dominant hi*hi */
            #pragma unroll
            for (int i = 0; i < 4; i++)
                #pragma unroll
                for (int j = 0; j < 2; j++) {
                    wmma::mma_sync(acc[i][j], al[i], bh[j], acc[i][j]);
                    wmma::mma_sync(acc[i][j], ah[i], bl[j], acc[i][j]);
                    wmma::mma_sync(acc[i][j], ah[i], bh[j], acc[i][j]);
                }
        }
        __syncthreads();
    }

    /* ---- epilogue: scale + store ---- */
    #pragma unroll
    for (int i = 0; i < 4; i++) {
        #pragma unroll
        for (int j = 0; j < 2; j++) {
            if (alpha != 1.0f) {
                #pragma unroll
                for (int t = 0; t < acc[i][j].num_elements; t++)
                    acc[i][j].x[t] *= alpha;
            }
            wmma::store_matrix_sync(
                &C[(size_t)(m0 + wm * 64 + i * 16) * ldc + n0 + wn * 32 + j * 16],
                acc[i][j], ldc, wmma::mem_row_major);
        }
    }
}

/* ---------------- LayerNorm over 512 elements, in place ---------------- */
__global__ __launch_bounds__(256) void ln_kernel(
    float* __restrict__ data, int stride,
    const float* __restrict__ g, const float* __restrict__ b)
{
    __shared__ float red[16];
    float* row = data + (size_t)blockIdx.x * stride;
    int tid = threadIdx.x;
    float x0 = row[tid];
    float x1 = row[tid + 256];
    float s  = x0 + x1;
    float sq = x0 * x0 + x1 * x1;
    #pragma unroll
    for (int o = 16; o > 0; o >>= 1) {
        s  += __shfl_xor_sync(0xffffffffu, s,  o);
        sq += __shfl_xor_sync(0xffffffffu, sq, o);
    }
    if ((tid & 31) == 0) { red[tid >> 5] = s; red[8 + (tid >> 5)] = sq; }
    __syncthreads();
    if (tid < 32) {
        float vs = (tid < 8) ? red[tid] : 0.0f;
        float vq = (tid < 8) ? red[8 + tid] : 0.0f;
        #pragma unroll
        for (int o = 4; o > 0; o >>= 1) {
            vs += __shfl_xor_sync(0xffffffffu, vs, o);
            vq += __shfl_xor_sync(0xffffffffu, vq, o);
        }
        if (tid == 0) { red[0] = vs; red[1] = vq; }
    }
    __syncthreads();
    float mean = red[0] * (1.0f / 512.0f);
    float var  = red[1] * (1.0f / 512.0f) - mean * mean;
    float rstd = rsqrtf(var + LN_EPS);
    row[tid]       = (x0 - mean) * rstd * g[tid]       + b[tid];
    row[tid + 256] = (x1 - mean) * rstd * g[tid + 256] + b[tid + 256];
}

/* ---------------- row softmax over 4096, in place ---------------- */
__global__ __launch_bounds__(256) void softmax_kernel(float* __restrict__ S)
{
    __shared__ float red[8];
    float* row = S + (size_t)blockIdx.x * SEQ_M;
    int tid = threadIdx.x;
    float v[16];
    float mx = -1e30f;
    #pragma unroll
    for (int i = 0; i < 16; i++) { v[i] = row[tid + i * 256]; mx = fmaxf(mx, v[i]); }
    #pragma unroll
    for (int o = 16; o > 0; o >>= 1) mx = fmaxf(mx, __shfl_xor_sync(0xffffffffu, mx, o));
    if ((tid & 31) == 0) red[tid >> 5] = mx;
    __syncthreads();
    if (tid < 32) {
        float m = (tid < 8) ? red[tid] : -1e30f;
        #pragma unroll
        for (int o = 4; o > 0; o >>= 1) m = fmaxf(m, __shfl_xor_sync(0xffffffffu, m, o));
        if (tid == 0) red[0] = m;
    }
    __syncthreads();
    mx = red[0];
    __syncthreads();
    float s = 0.0f;
    #pragma unroll
    for (int i = 0; i < 16; i++) { v[i] = __expf(v[i] - mx); s += v[i]; }
    #pragma unroll
    for (int o = 16; o > 0; o >>= 1) s += __shfl_xor_sync(0xffffffffu, s, o);
    if ((tid & 31) == 0) red[tid >> 5] = s;
    __syncthreads();
    if (tid < 32) {
        float m = (tid < 8) ? red[tid] : 0.0f;
        #pragma unroll
        for (int o = 4; o > 0; o >>= 1) m += __shfl_xor_sync(0xffffffffu, m, o);
        if (tid == 0) red[0] = m;
    }
    __syncthreads();
    float inv = 1.0f / red[0];
    #pragma unroll
    for (int i = 0; i < 16; i++) row[tid + i * 256] = v[i] * inv;
}

/* ---------------- bias add on final output ---------------- */
__global__ __launch_bounds__(256) void bias_kernel(float* __restrict__ out,
                                                   const float* __restrict__ bo)
{
    size_t i = (size_t)blockIdx.x * 256 + threadIdx.x;
    out[i] += bo[i & (DIM - 1)];
}

/* ---------------- launcher ---------------- */
extern "C" void kernel_launch(void* const* d_in, const int* in_sizes, int n_in,
                              void* d_out, int out_size)
{
    const float* x    = (const float*)d_in[0];
    const float* ctx  = (const float*)d_in[1];
    const float* Wq   = (const float*)d_in[2];
    const float* Wkv  = (const float*)d_in[3];
    const float* Wo   = (const float*)d_in[4];
    const float* bo   = (const float*)d_in[5];
    const float* ln_g = (const float*)d_in[6];
    const float* ln_b = (const float*)d_in[7];
    float* out = (float*)d_out;

    float *q, *kv, *S, *O;
    cudaGetSymbolAddress((void**)&q,  g_q);
    cudaGetSymbolAddress((void**)&kv, g_kv);
    cudaGetSymbolAddress((void**)&S,  g_S);
    cudaGetSymbolAddress((void**)&O,  g_O);

    dim3 blk(256);

    /* q = x @ Wq : [16384,512] */
    gemm_tf32x3<false><<<dim3(DIM / BN, ROWS / BM, 1), blk>>>(
        x, Wq, q, ROWS, DIM, DIM, DIM, DIM, DIM, 0, 0, 0, 1.0f);

    /* kv = ctx @ Wkv : [16384,1024] */
    gemm_tf32x3<false><<<dim3(2 * DIM / BN, ROWS / BM, 1), blk>>>(
        ctx, Wkv, kv, ROWS, 2 * DIM, DIM, DIM, 2 * DIM, 2 * DIM, 0, 0, 0, 1.0f);

    /* qk-norm (in place; k lives in first 512 cols of kv) */
    ln_kernel<<<ROWS, 256>>>(q, DIM, ln_g, ln_b);
    ln_kernel<<<ROWS, 256>>>(kv, 2 * DIM, ln_g, ln_b);

    /* S = scale * q @ k^T */
    gemm_tf32x3<true><<<dim3(SEQ_M / BN, SEQ_N / BM, BATCH), blk>>>(
        q, kv, S,
        SEQ_N, SEQ_M, DIM, DIM, 2 * DIM, SEQ_M,
        (long long)SEQ_N * DIM, (long long)SEQ_M * 2 * DIM,
        (long long)SEQ_N * SEQ_M, ATTN_SCALE);

    /* P = softmax(S) in place */
    softmax_kernel<<<BATCH * SEQ_N, 256>>>(S);

    /* O = P @ v */
    gemm_tf32x3<false><<<dim3(DIM / BN, SEQ_N / BM, BATCH), blk>>>(
        S, kv + DIM, O,
        SEQ_N, DIM, SEQ_M, SEQ_M, 2 * DIM, DIM,
        (long long)SEQ_N * SEQ_M, (long long)SEQ_M * 2 * DIM,
        (long long)SEQ_N * DIM, 1.0f);

    /* out = O @ Wo (+ bo) */
    gemm_tf32x3<false><<<dim3(DIM / BN, ROWS / BM, 1), blk>>>(
        O, Wo, out, ROWS, DIM, DIM, DIM, DIM, DIM, 0, 0, 0, 1.0f);
    bias_kernel<<<(ROWS * DIM) / 256, 256>>>(out, bo);
}

// round 3
// speedup vs baseline: 3.3521x; 3.3521x over previous
#include <cuda_runtime.h>
#include <cuda_bf16.h>
#include <mma.h>

using namespace nvcuda;
typedef __nv_bfloat16 bf16;

#define BATCH 4
#define SEQ   4096
#define DIM   512
#define ROWS  16384
#define ATTN_SCALE 0.125f
#define LN_EPS 1e-5f

/* ---------------- scratch (no allocations allowed) ---------------- */
__device__ __align__(256) float g_q [(size_t)ROWS * DIM];
__device__ __align__(256) float g_kv[(size_t)ROWS * 2 * DIM];
__device__ __align__(256) float g_S [(size_t)BATCH * SEQ * SEQ];

__device__ __align__(256) bf16 g_xh[(size_t)ROWS * DIM];
__device__ __align__(256) bf16 g_xl[(size_t)ROWS * DIM];
__device__ __align__(256) bf16 g_ch[(size_t)ROWS * DIM];
__device__ __align__(256) bf16 g_cl[(size_t)ROWS * DIM];
__device__ __align__(256) bf16 g_wqh[DIM * DIM];
__device__ __align__(256) bf16 g_wql[DIM * DIM];
__device__ __align__(256) bf16 g_wkvh[DIM * 2 * DIM];
__device__ __align__(256) bf16 g_wkvl[DIM * 2 * DIM];
__device__ __align__(256) bf16 g_woh[DIM * DIM];
__device__ __align__(256) bf16 g_wol[DIM * DIM];
__device__ __align__(256) bf16 g_qh[(size_t)ROWS * DIM];
__device__ __align__(256) bf16 g_ql[(size_t)ROWS * DIM];
__device__ __align__(256) bf16 g_kh[(size_t)ROWS * DIM];
__device__ __align__(256) bf16 g_kl[(size_t)ROWS * DIM];
__device__ __align__(256) bf16 g_vh[(size_t)ROWS * DIM];
__device__ __align__(256) bf16 g_vl[(size_t)ROWS * DIM];
__device__ __align__(256) bf16 g_ph[(size_t)BATCH * SEQ * SEQ];
__device__ __align__(256) bf16 g_pl[(size_t)BATCH * SEQ * SEQ];
__device__ __align__(256) bf16 g_oh[(size_t)ROWS * DIM];
__device__ __align__(256) bf16 g_ol[(size_t)ROWS * DIM];

/* ---------------- cp.async helpers ---------------- */
__device__ __forceinline__ unsigned smem_u32(const void* p) {
    return (unsigned)__cvta_generic_to_shared(p);
}
#define CPA16(dst, src) \
    asm volatile("cp.async.cg.shared.global [%0], [%1], 16;\n" :: "r"(dst), "l"(src))
#define CPCOMMIT() asm volatile("cp.async.commit_group;\n" ::)
template<int N> __device__ __forceinline__ void cpwait() {
    asm volatile("cp.async.wait_group %0;\n" :: "n"(N));
}

/* ---------------- bf16x3 GEMM ----------------
 * C = alpha * (Ah+Al) @ (Bh+Bl), dropping Al*Bl.
 * A row-major [M,K]. If B_COL, B given as [N,K] row-major (=> col-major K,N).
 * 128x128x32 block tile, 256 threads, 8 warps of 64x32 (m16n16k16 frags).
 * 2-stage cp.async pipeline. Epilogue through smem; optionally splits output
 * into bf16 hi/lo, optionally adds bias.
 */
#define BM 128
#define BN 128
#define BK 32
#define AST 40    /* A-tile smem row stride (bf16 elems) */
#define BST 136   /* row-major B-tile smem row stride   */
#define NT  256

__device__ __forceinline__ void stage_Atile(unsigned sm, const bf16* g, int ld, int tid) {
    /* 128 rows x 32 cols bf16, 16B chunks: 512 chunks, 2 per thread */
    #pragma unroll
    for (int i = 0; i < 2; i++) {
        int idx = i * NT + tid;
        int r = idx >> 2, c = (idx & 3) * 8;
        CPA16(sm + (unsigned)(r * AST + c) * 2, g + (size_t)r * ld + c);
    }
}
__device__ __forceinline__ void stage_Brm(unsigned sm, const bf16* g, int ld, int tid) {
    /* 32 rows x 128 cols bf16 */
    #pragma unroll
    for (int i = 0; i < 2; i++) {
        int idx = i * NT + tid;
        int r = idx >> 4, c = (idx & 15) * 8;
        CPA16(sm + (unsigned)(r * BST + c) * 2, g + (size_t)r * ld + c);
    }
}

template<bool B_COL, bool SPLIT, bool BIAS>
__global__ __launch_bounds__(NT, 2) void gemm_bf16x3(
    const bf16* __restrict__ Ah, const bf16* __restrict__ Al,
    const bf16* __restrict__ Bh, const bf16* __restrict__ Bl,
    float* __restrict__ C, bf16* __restrict__ Ch, bf16* __restrict__ Cl,
    const float* __restrict__ bias,
    int M, int N, int K, int lda, int ldb, int ldc,
    long long sA, long long sB, long long sC, float alpha)
{
    extern __shared__ char smem[];
    const int tid  = threadIdx.x;
    const int warp = tid >> 5;
    const int wm = warp >> 2;   /* 0..1 */
    const int wn = warp & 3;    /* 0..3 */
    const int m0 = blockIdx.y * BM;
    const int n0 = blockIdx.x * BN;
    const long long zb = blockIdx.z;

    const int ASZ = BM * AST * 2;         /* 10240 B */
    const int STG = 4 * ASZ;              /* 40960 B per stage */
    unsigned sbase = smem_u32(smem);

    const bf16* gAh = Ah + zb * sA + (size_t)m0 * lda;
    const bf16* gAl = Al + zb * sA + (size_t)m0 * lda;
    const bf16* gBh;
    const bf16* gBl;
    if (B_COL) { gBh = Bh + zb * sB + (size_t)n0 * ldb; gBl = Bl + zb * sB + (size_t)n0 * ldb; }
    else       { gBh = Bh + zb * sB + n0;               gBl = Bl + zb * sB + n0; }

    auto stage = [&](int s, int k0) {
        unsigned sp = sbase + (unsigned)(s * STG);
        stage_Atile(sp,            gAh + k0, lda, tid);
        stage_Atile(sp + ASZ,      gAl + k0, lda, tid);
        if (B_COL) {
            stage_Atile(sp + 2*ASZ, gBh + k0, ldb, tid);
            stage_Atile(sp + 3*ASZ, gBl + k0, ldb, tid);
        } else {
            stage_Brm(sp + 2*ASZ, gBh + (size_t)k0 * ldb, ldb, tid);
            stage_Brm(sp + 3*ASZ, gBl + (size_t)k0 * ldb, ldb, tid);
        }
        CPCOMMIT();
    };

    wmma::fragment<wmma::accumulator, 16, 16, 16, float> acc[4][2];
    #pragma unroll
    for (int i = 0; i < 4; i++)
        #pragma unroll
        for (int j = 0; j < 2; j++)
            wmma::fill_fragment(acc[i][j], 0.0f);

    stage(0, 0);
    int s = 0;
    for (int k0 = 0; k0 < K; k0 += BK) {
        if (k0 + BK < K) { stage(s ^ 1, k0 + BK); cpwait<1>(); }
        else             { cpwait<0>(); }
        __syncthreads();

        char* sp  = smem + s * STG;
        bf16* sAh = (bf16*)sp;
        bf16* sAl = (bf16*)(sp + ASZ);
        bf16* sBh = (bf16*)(sp + 2 * ASZ);
        bf16* sBl = (bf16*)(sp + 3 * ASZ);

        #pragma unroll
        for (int kk = 0; kk < BK; kk += 16) {
            wmma::fragment<wmma::matrix_a, 16, 16, 16, bf16, wmma::row_major> a[4];
            #pragma unroll
            for (int i = 0; i < 4; i++)
                wmma::load_matrix_sync(a[i], sAh + (wm * 64 + i * 16) * AST + kk, AST);

            if (B_COL) {
                wmma::fragment<wmma::matrix_b, 16, 16, 16, bf16, wmma::col_major> bh[2], bl[2];
                #pragma unroll
                for (int j = 0; j < 2; j++) {
                    wmma::load_matrix_sync(bh[j], sBh + (wn * 32 + j * 16) * AST + kk, AST);
                    wmma::load_matrix_sync(bl[j], sBl + (wn * 32 + j * 16) * AST + kk, AST);
                }
                #pragma unroll
                for (int i = 0; i < 4; i++)
                    #pragma unroll
                    for (int j = 0; j < 2; j++) {
                        wmma::mma_sync(acc[i][j], a[i], bh[j], acc[i][j]);
                        wmma::mma_sync(acc[i][j], a[i], bl[j], acc[i][j]);
                    }
                #pragma unroll
                for (int i = 0; i < 4; i++)
                    wmma::load_matrix_sync(a[i], sAl + (wm * 64 + i * 16) * AST + kk, AST);
                #pragma unroll
                for (int i = 0; i < 4; i++)
                    #pragma unroll
                    for (int j = 0; j < 2; j++)
                        wmma::mma_sync(acc[i][j], a[i], bh[j], acc[i][j]);
            } else {
                wmma::fragment<wmma::matrix_b, 16, 16, 16, bf16, wmma::row_major> bh[2], bl[2];
                #pragma unroll
                for (int j = 0; j < 2; j++) {
                    wmma::load_matrix_sync(bh[j], sBh + kk * BST + wn * 32 + j * 16, BST);
                    wmma::load_matrix_sync(bl[j], sBl + kk * BST + wn * 32 + j * 16, BST);
                }
                #pragma unroll
                for (int i = 0; i < 4; i++)
                    #pragma unroll
                    for (int j = 0; j < 2; j++) {
                        wmma::mma_sync(acc[i][j], a[i], bh[j], acc[i][j]);
                        wmma::mma_sync(acc[i][j], a[i], bl[j], acc[i][j]);
                    }
                #pragma unroll
                for (int i = 0; i < 4; i++)
                    wmma::load_matrix_sync(a[i], sAl + (wm * 64 + i * 16) * AST + kk, AST);
                #pragma unroll
                for (int i = 0; i < 4; i++)
                    #pragma unroll
                    for (int j = 0; j < 2; j++)
                        wmma::mma_sync(acc[i][j], a[i], bh[j], acc[i][j]);
            }
        }
        __syncthreads();
        s ^= 1;
    }

    /* ---- epilogue through smem (reuse stage buffers: 128x132 fp32) ---- */
    float* cs = (float*)smem;
    #pragma unroll
    for (int i = 0; i < 4; i++)
        #pragma unroll
        for (int j = 0; j < 2; j++) {
            #pragma unroll
            for (int t = 0; t < acc[i][j].num_elements; t++)
                acc[i][j].x[t] *= alpha;
            wmma::store_matrix_sync(cs + (wm * 64 + i * 16) * 132 + wn * 32 + j * 16,
                                    acc[i][j], 132, wmma::mem_row_major);
        }
    __syncthreads();

    #pragma unroll
    for (int it = 0; it < 16; it++) {
        int idx = it * NT + tid;        /* 0..4095 float4 slots */
        int r = idx >> 5, c4 = (idx & 31) * 4;
        float4 v = *(float4*)(cs + r * 132 + c4);
        if (BIAS) {
            v.x += bias[n0 + c4 + 0];
            v.y += bias[n0 + c4 + 1];
            v.z += bias[n0 + c4 + 2];
            v.w += bias[n0 + c4 + 3];
        }
        size_t base = (size_t)zb * sC + (size_t)(m0 + r) * ldc + n0 + c4;
        if (SPLIT) {
            bf16 h0 = __float2bfloat16(v.x), h1 = __float2bfloat16(v.y);
            bf16 h2 = __float2bfloat16(v.z), h3 = __float2bfloat16(v.w);
            bf16 l0 = __float2bfloat16(v.x - __bfloat162float(h0));
            bf16 l1 = __float2bfloat16(v.y - __bfloat162float(h1));
            bf16 l2 = __float2bfloat16(v.z - __bfloat162float(h2));
            bf16 l3 = __float2bfloat16(v.w - __bfloat162float(h3));
            __nv_bfloat162* H = (__nv_bfloat162*)(Ch + base);
            __nv_bfloat162* L = (__nv_bfloat162*)(Cl + base);
            __nv_bfloat162 t;
            t.x = h0; t.y = h1; H[0] = t;
            t.x = h2; t.y = h3; H[1] = t;
            t.x = l0; t.y = l1; L[0] = t;
            t.x = l2; t.y = l3; L[1] = t;
        } else {
            *(float4*)(C + base) = v;
        }
    }
}

/* ---------------- fp32 -> bf16 hi/lo split (contiguous) ---------------- */
__global__ __launch_bounds__(256) void split_kernel(
    const float* __restrict__ in, bf16* __restrict__ h, bf16* __restrict__ l, size_t n4)
{
    size_t i = (size_t)blockIdx.x * 256 + threadIdx.x;
    if (i >= n4) return;
    float4 v = ((const float4*)in)[i];
    bf16 h0 = __float2bfloat16(v.x), h1 = __float2bfloat16(v.y);
    bf16 h2 = __float2bfloat16(v.z), h3 = __float2bfloat16(v.w);
    __nv_bfloat162 t;
    __nv_bfloat162* H = (__nv_bfloat162*)(h + i * 4);
    __nv_bfloat162* L = (__nv_bfloat162*)(l + i * 4);
    t.x = h0; t.y = h1; H[0] = t;
    t.x = h2; t.y = h3; H[1] = t;
    t.x = __float2bfloat16(v.x - __bfloat162float(h0));
    t.y = __float2bfloat16(v.y - __bfloat162float(h1)); L[0] = t;
    t.x = __float2bfloat16(v.z - __bfloat162float(h2));
    t.y = __float2bfloat16(v.w - __bfloat162float(h3)); L[1] = t;
}

/* ---------------- strided split (for v inside kv) ---------------- */
__global__ __launch_bounds__(128) void split_strided_kernel(
    const float* __restrict__ in, int istride,
    bf16* __restrict__ h, bf16* __restrict__ l)
{
    const float* row = in + (size_t)blockIdx.x * istride;
    bf16* hr = h + (size_t)blockIdx.x * DIM;
    bf16* lr = l + (size_t)blockIdx.x * DIM;
    int c = threadIdx.x * 4;
    float4 v = *(const float4*)(row + c);
    bf16 h0 = __float2bfloat16(v.x), h1 = __float2bfloat16(v.y);
    bf16 h2 = __float2bfloat16(v.z), h3 = __float2bfloat16(v.w);
    __nv_bfloat162 t;
    __nv_bfloat162* H = (__nv_bfloat162*)(hr + c);
    __nv_bfloat162* L = (__nv_bfloat162*)(lr + c);
    t.x = h0; t.y = h1; H[0] = t;
    t.x = h2; t.y = h3; H[1] = t;
    t.x = __float2bfloat16(v.x - __bfloat162float(h0));
    t.y = __float2bfloat16(v.y - __bfloat162float(h1)); L[0] = t;
    t.x = __float2bfloat16(v.z - __bfloat162float(h2));
    t.y = __float2bfloat16(v.w - __bfloat162float(h3)); L[1] = t;
}

/* ---------------- LayerNorm(512) fp32 in -> split bf16 out ---------------- */
__global__ __launch_bounds__(256) void ln_split_kernel(
    const float* __restrict__ in, int istride,
    bf16* __restrict__ oh, bf16* __restrict__ ol,
    const float* __restrict__ g, const float* __restrict__ b)
{
    __shared__ float red[16];
    const float* row = in + (size_t)blockIdx.x * istride;
    bf16* hr = oh + (size_t)blockIdx.x * DIM;
    bf16* lr = ol + (size_t)blockIdx.x * DIM;
    int tid = threadIdx.x;
    float x0 = row[tid];
    float x1 = row[tid + 256];
    float s  = x0 + x1;
    float sq = x0 * x0 + x1 * x1;
    #pragma unroll
    for (int o = 16; o > 0; o >>= 1) {
        s  += __shfl_xor_sync(0xffffffffu, s,  o);
        sq += __shfl_xor_sync(0xffffffffu, sq, o);
    }
    if ((tid & 31) == 0) { red[tid >> 5] = s; red[8 + (tid >> 5)] = sq; }
    __syncthreads();
    if (tid < 32) {
        float vs = (tid < 8) ? red[tid] : 0.0f;
        float vq = (tid < 8) ? red[8 + tid] : 0.0f;
        #pragma unroll
        for (int o = 4; o > 0; o >>= 1) {
            vs += __shfl_xor_sync(0xffffffffu, vs, o);
            vq += __shfl_xor_sync(0xffffffffu, vq, o);
        }
        if (tid == 0) { red[0] = vs; red[1] = vq; }
    }
    __syncthreads();
    float mean = red[0] * (1.0f / 512.0f);
    float var  = red[1] * (1.0f / 512.0f) - mean * mean;
    float rstd = rsqrtf(var + LN_EPS);
    float y0 = (x0 - mean) * rstd * g[tid]       + b[tid];
    float y1 = (x1 - mean) * rstd * g[tid + 256] + b[tid + 256];
    bf16 h0 = __float2bfloat16(y0);
    bf16 h1 = __float2bfloat16(y1);
    hr[tid]       = h0;
    hr[tid + 256] = h1;
    lr[tid]       = __float2bfloat16(y0 - __bfloat162float(h0));
    lr[tid + 256] = __float2bfloat16(y1 - __bfloat162float(h1));
}

/* ---------------- softmax(4096) fp32 in -> split bf16 out ---------------- */
__global__ __launch_bounds__(256) void softmax_split_kernel(
    const float* __restrict__ S, bf16* __restrict__ ph, bf16* __restrict__ pl)
{
    __shared__ float red[8];
    const float* row = S + (size_t)blockIdx.x * SEQ;
    bf16* hr = ph + (size_t)blockIdx.x * SEQ;
    bf16* lr = pl + (size_t)blockIdx.x * SEQ;
    int tid = threadIdx.x;
    float v[16];
    float mx = -1e30f;
    #pragma unroll
    for (int i = 0; i < 16; i++) { v[i] = row[tid + i * 256]; mx = fmaxf(mx, v[i]); }
    #pragma unroll
    for (int o = 16; o > 0; o >>= 1) mx = fmaxf(mx, __shfl_xor_sync(0xffffffffu, mx, o));
    if ((tid & 31) == 0) red[tid >> 5] = mx;
    __syncthreads();
    if (tid < 32) {
        float m = (tid < 8) ? red[tid] : -1e30f;
        #pragma unroll
        for (int o = 4; o > 0; o >>= 1) m = fmaxf(m, __shfl_xor_sync(0xffffffffu, m, o));
        if (tid == 0) red[0] = m;
    }
    __syncthreads();
    mx = red[0];
    __syncthreads();
    float s = 0.0f;
    #pragma unroll
    for (int i = 0; i < 16; i++) { v[i] = __expf(v[i] - mx); s += v[i]; }
    #pragma unroll
    for (int o = 16; o > 0; o >>= 1) s += __shfl_xor_sync(0xffffffffu, s, o);
    if ((tid & 31) == 0) red[tid >> 5] = s;
    __syncthreads();
    if (tid < 32) {
        float m = (tid < 8) ? red[tid] : 0.0f;
        #pragma unroll
        for (int o = 4; o > 0; o >>= 1) m += __shfl_xor_sync(0xffffffffu, m, o);
        if (tid == 0) red[0] = m;
    }
    __syncthreads();
    float inv = 1.0f / red[0];
    #pragma unroll
    for (int i = 0; i < 16; i++) {
        float p = v[i] * inv;
        bf16 h = __float2bfloat16(p);
        hr[tid + i * 256] = h;
        lr[tid + i * 256] = __float2bfloat16(p - __bfloat162float(h));
    }
}

/* ---------------- launcher ---------------- */
#define SMEM_BYTES 81920

extern "C" void kernel_launch(void* const* d_in, const int* in_sizes, int n_in,
                              void* d_out, int out_size)
{
    const float* x    = (const float*)d_in[0];
    const float* ctx  = (const float*)d_in[1];
    const float* Wq   = (const float*)d_in[2];
    const float* Wkv  = (const float*)d_in[3];
    const float* Wo   = (const float*)d_in[4];
    const float* bo   = (const float*)d_in[5];
    const float* ln_g = (const float*)d_in[6];
    const float* ln_b = (const float*)d_in[7];
    float* out = (float*)d_out;

    float *q, *kv, *S;
    bf16 *xh, *xl, *ch, *cl, *wqh, *wql, *wkvh, *wkvl, *woh, *wol;
    bf16 *qh, *ql, *kh, *kl, *vh, *vl, *ph, *pl, *oh, *ol;
    cudaGetSymbolAddress((void**)&q,   g_q);
    cudaGetSymbolAddress((void**)&kv,  g_kv);
    cudaGetSymbolAddress((void**)&S,   g_S);
    cudaGetSymbolAddress((void**)&xh,  g_xh);   cudaGetSymbolAddress((void**)&xl,  g_xl);
    cudaGetSymbolAddress((void**)&ch,  g_ch);   cudaGetSymbolAddress((void**)&cl,  g_cl);
    cudaGetSymbolAddress((void**)&wqh, g_wqh);  cudaGetSymbolAddress((void**)&wql, g_wql);
    cudaGetSymbolAddress((void**)&wkvh,g_wkvh); cudaGetSymbolAddress((void**)&wkvl,g_wkvl);
    cudaGetSymbolAddress((void**)&woh, g_woh);  cudaGetSymbolAddress((void**)&wol, g_wol);
    cudaGetSymbolAddress((void**)&qh,  g_qh);   cudaGetSymbolAddress((void**)&ql,  g_ql);
    cudaGetSymbolAddress((void**)&kh,  g_kh);   cudaGetSymbolAddress((void**)&kl,  g_kl);
    cudaGetSymbolAddress((void**)&vh,  g_vh);   cudaGetSymbolAddress((void**)&vl,  g_vl);
    cudaGetSymbolAddress((void**)&ph,  g_ph);   cudaGetSymbolAddress((void**)&pl,  g_pl);
    cudaGetSymbolAddress((void**)&oh,  g_oh);   cudaGetSymbolAddress((void**)&ol,  g_ol);

    cudaFuncSetAttribute(gemm_bf16x3<false,false,false>,
                         cudaFuncAttributeMaxDynamicSharedMemorySize, SMEM_BYTES);
    cudaFuncSetAttribute(gemm_bf16x3<true,false,false>,
                         cudaFuncAttributeMaxDynamicSharedMemorySize, SMEM_BYTES);
    cudaFuncSetAttribute(gemm_bf16x3<false,true,false>,
                         cudaFuncAttributeMaxDynamicSharedMemorySize, SMEM_BYTES);
    cudaFuncSetAttribute(gemm_bf16x3<false,false,true>,
                         cudaFuncAttributeMaxDynamicSharedMemorySize, SMEM_BYTES);

    /* split inputs */
    split_kernel<<<(ROWS * DIM / 4 + 255) / 256, 256>>>(x,   xh,  xl,  (size_t)ROWS * DIM / 4);
    split_kernel<<<(ROWS * DIM / 4 + 255) / 256, 256>>>(ctx, ch,  cl,  (size_t)ROWS * DIM / 4);
    split_kernel<<<(DIM * DIM / 4 + 255) / 256, 256>>>(Wq,  wqh, wql, (size_t)DIM * DIM / 4);
    split_kernel<<<(DIM * 2 * DIM / 4 + 255) / 256, 256>>>(Wkv, wkvh, wkvl, (size_t)DIM * 2 * DIM / 4);
    split_kernel<<<(DIM * DIM / 4 + 255) / 256, 256>>>(Wo,  woh, wol, (size_t)DIM * DIM / 4);

    /* q = x @ Wq (fp32 out) */
    gemm_bf16x3<false,false,false><<<dim3(DIM / BN, ROWS / BM, 1), NT, SMEM_BYTES>>>(
        xh, xl, wqh, wql, q, nullptr, nullptr, nullptr,
        ROWS, DIM, DIM, DIM, DIM, DIM, 0, 0, 0, 1.0f);

    /* kv = ctx @ Wkv (fp32 out) */
    gemm_bf16x3<false,false,false><<<dim3(2 * DIM / BN, ROWS / BM, 1), NT, SMEM_BYTES>>>(
        ch, cl, wkvh, wkvl, kv, nullptr, nullptr, nullptr,
        ROWS, 2 * DIM, DIM, DIM, 2 * DIM, 2 * DIM, 0, 0, 0, 1.0f);

    /* LN(q) -> qh/ql ; LN(k) -> kh/kl ; split v */
    ln_split_kernel<<<ROWS, 256>>>(q,  DIM,     qh, ql, ln_g, ln_b);
    ln_split_kernel<<<ROWS, 256>>>(kv, 2 * DIM, kh, kl, ln_g, ln_b);
    split_strided_kernel<<<ROWS, 128>>>(kv + DIM, 2 * DIM, vh, vl);

    /* S = scale * q @ k^T (fp32 out) */
    gemm_bf16x3<true,false,false><<<dim3(SEQ / BN, SEQ / BM, BATCH), NT, SMEM_BYTES>>>(
        qh, ql, kh, kl, S, nullptr, nullptr, nullptr,
        SEQ, SEQ, DIM, DIM, DIM, SEQ,
        (long long)SEQ * DIM, (long long)SEQ * DIM, (long long)SEQ * SEQ, ATTN_SCALE);

    /* P = softmax(S) -> ph/pl */
    softmax_split_kernel<<<BATCH * SEQ, 256>>>(S, ph, pl);

    /* O = P @ v (split bf16 out) */
    gemm_bf16x3<false,true,false><<<dim3(DIM / BN, SEQ / BM, BATCH), NT, SMEM_BYTES>>>(
        ph, pl, vh, vl, nullptr, oh, ol, nullptr,
        SEQ, DIM, SEQ, SEQ, DIM, DIM,
        (long long)SEQ * SEQ, (long long)SEQ * DIM, (long long)SEQ * DIM, 1.0f);

    /* out = O @ Wo + bo (fp32 out, bias fused) */
    gemm_bf16x3<false,false,true><<<dim3(DIM / BN, ROWS / BM, 1), NT, SMEM_BYTES>>>(
        oh, ol, woh, wol, out, nullptr, nullptr, bo,
        ROWS, DIM, DIM, DIM, DIM, DIM, 0, 0, 0, 1.0f);
}

// round 5
// speedup vs baseline: 4.7067x; 1.4041x over previous
#include <cuda_runtime.h>
#include <cuda_bf16.h>
#include <cuda_fp16.h>
#include <mma.h>
#include <cstdint>

using namespace nvcuda;
typedef __nv_bfloat16 bf16;

#define BATCH 4
#define SEQ   4096
#define DIM   512
#define ROWS  16384
#define ATTN_SCALE 0.125f
#define LN_EPS 1e-5f

/* ---------------- scratch (no allocations allowed) ---------------- */
__device__ __align__(256) float g_q [(size_t)ROWS * DIM];
__device__ __align__(256) float g_kv[(size_t)ROWS * 2 * DIM];
__device__ __align__(256) float g_S [(size_t)BATCH * SEQ * SEQ];

__device__ __align__(256) bf16 g_xh [(size_t)ROWS * DIM];
__device__ __align__(256) bf16 g_xl [(size_t)ROWS * DIM];
__device__ __align__(256) bf16 g_ch [(size_t)ROWS * DIM];
__device__ __align__(256) bf16 g_cl [(size_t)ROWS * DIM];
__device__ __align__(256) bf16 g_wqth [DIM * DIM];
__device__ __align__(256) bf16 g_wqtl [DIM * DIM];
__device__ __align__(256) bf16 g_wkvth[2 * DIM * DIM];
__device__ __align__(256) bf16 g_wkvtl[2 * DIM * DIM];
__device__ __align__(256) bf16 g_woth [DIM * DIM];
__device__ __align__(256) bf16 g_wotl [DIM * DIM];
__device__ __align__(256) bf16 g_oh [(size_t)ROWS * DIM];
__device__ __align__(256) bf16 g_ol [(size_t)ROWS * DIM];

__device__ __align__(256) __half g_qh [(size_t)ROWS * DIM];
__device__ __align__(256) __half g_ql [(size_t)ROWS * DIM];
__device__ __align__(256) __half g_kh [(size_t)ROWS * DIM];          /* single */
__device__ __align__(256) __half g_vt [(size_t)BATCH * DIM * SEQ];   /* v^T, single */
__device__ __align__(256) __half g_ph [(size_t)BATCH * SEQ * SEQ];
__device__ __align__(256) __half g_pl [(size_t)BATCH * SEQ * SEQ];

/* ---------------- cp.async helpers ---------------- */
__device__ __forceinline__ unsigned smem_u32(const void* p) {
    return (unsigned)__cvta_generic_to_shared(p);
}
#define CPA16(dst, src) \
    asm volatile("cp.async.cg.shared.global [%0], [%1], 16;\n" :: "r"(dst), "l"(src))
#define CPCOMMIT() asm volatile("cp.async.commit_group;\n" ::)
template<int N> __device__ __forceinline__ void cpwait() {
    asm volatile("cp.async.wait_group %0;\n" :: "n"(N));
}

/* ---------------- hi/lo GEMM ----------------
 * C[M,N] = alpha * (Ah+Al)[M,K] @ B^T  where B is [N,K] row-major.
 * THREE: B = Bh+Bl, 3 MMAs (drop Al*Bl).  !THREE: B single, 2 MMAs.
 * 128x128x32 tiles, 256 thr, 8 warps of 64x32 (m16n16k16), 2-stage cp.async.
 */
#define BM 128
#define BN 128
#define BK 32
#define AST 40                         /* smem row stride, elems */
#define NT  256
#define TSZ 10240u                     /* one tile bytes: 128*40*2 */
#define SMEM_BYTES 81920               /* 2 stages x 4 tiles max */

template<typename T>
__device__ __forceinline__ void stage_tile(unsigned sm, const T* g, int ld, int tid) {
    #pragma unroll
    for (int i = 0; i < 2; i++) {
        int idx = i * NT + tid;
        int r = idx >> 2, c = (idx & 3) * 8;
        CPA16(sm + (unsigned)(r * AST + c) * 2, g + (size_t)r * ld + c);
    }
}

template<typename T, bool THREE, bool SPLIT, bool BIAS>
__global__ __launch_bounds__(NT, 2) void gemm_hilo(
    const T* __restrict__ Ah, const T* __restrict__ Al,
    const T* __restrict__ Bh, const T* __restrict__ Bl,
    float* __restrict__ C, bf16* __restrict__ Ch, bf16* __restrict__ Cl,
    const float* __restrict__ bias,
    int K, int lda, int ldb, int ldc,
    long long sA, long long sB, long long sC, float alpha)
{
    extern __shared__ char smem[];
    const int tid  = threadIdx.x;
    const int warp = tid >> 5;
    const int wm = warp >> 2;
    const int wn = warp & 3;
    const int m0 = blockIdx.y * BM;
    const int n0 = blockIdx.x * BN;
    const long long zb = blockIdx.z;
    const unsigned STG = (THREE ? 4u : 3u) * TSZ;
    const unsigned sb0 = smem_u32(smem);

    const T* gAh = Ah + zb * sA + (size_t)m0 * lda;
    const T* gAl = Al + zb * sA + (size_t)m0 * lda;
    const T* gBh = Bh + zb * sB + (size_t)n0 * ldb;
    const T* gBl = THREE ? (Bl + zb * sB + (size_t)n0 * ldb) : nullptr;

    wmma::fragment<wmma::accumulator, 16, 16, 16, float> acc[4][2];
    #pragma unroll
    for (int i = 0; i < 4; i++)
        #pragma unroll
        for (int j = 0; j < 2; j++)
            wmma::fill_fragment(acc[i][j], 0.0f);

    auto stage = [&](int s, int k0) {
        unsigned sp = sb0 + (unsigned)s * STG;
        stage_tile(sp,            gAh + k0, lda, tid);
        stage_tile(sp + TSZ,      gAl + k0, lda, tid);
        stage_tile(sp + 2u * TSZ, gBh + k0, ldb, tid);
        if (THREE) stage_tile(sp + 3u * TSZ, gBl + k0, ldb, tid);
        CPCOMMIT();
    };

    stage(0, 0);
    int s = 0;
    for (int k0 = 0; k0 < K; k0 += BK) {
        if (k0 + BK < K) { stage(s ^ 1, k0 + BK); cpwait<1>(); }
        else             { cpwait<0>(); }
        __syncthreads();

        T* sAh = (T*)(smem + s * STG);
        T* sAl = (T*)(smem + s * STG + TSZ);
        T* sBh = (T*)(smem + s * STG + 2 * TSZ);
        T* sBl = (T*)(smem + s * STG + 3 * TSZ);

        #pragma unroll
        for (int kk = 0; kk < BK; kk += 16) {
            wmma::fragment<wmma::matrix_a, 16, 16, 16, T, wmma::row_major> a[4];
            wmma::fragment<wmma::matrix_b, 16, 16, 16, T, wmma::col_major> bh[2];
            #pragma unroll
            for (int i = 0; i < 4; i++)
                wmma::load_matrix_sync(a[i], sAh + (wm * 64 + i * 16) * AST + kk, AST);
            #pragma unroll
            for (int j = 0; j < 2; j++)
                wmma::load_matrix_sync(bh[j], sBh + (wn * 32 + j * 16) * AST + kk, AST);

            if (THREE) {
                wmma::fragment<wmma::matrix_b, 16, 16, 16, T, wmma::col_major> bl[2];
                #pragma unroll
                for (int j = 0; j < 2; j++)
                    wmma::load_matrix_sync(bl[j], sBl + (wn * 32 + j * 16) * AST + kk, AST);
                #pragma unroll
                for (int i = 0; i < 4; i++)
                    #pragma unroll
                    for (int j = 0; j < 2; j++) {
                        wmma::mma_sync(acc[i][j], a[i], bh[j], acc[i][j]);
                        wmma::mma_sync(acc[i][j], a[i], bl[j], acc[i][j]);
                    }
            } else {
                #pragma unroll
                for (int i = 0; i < 4; i++)
                    #pragma unroll
                    for (int j = 0; j < 2; j++)
                        wmma::mma_sync(acc[i][j], a[i], bh[j], acc[i][j]);
            }
            #pragma unroll
            for (int i = 0; i < 4; i++)
                wmma::load_matrix_sync(a[i], sAl + (wm * 64 + i * 16) * AST + kk, AST);
            #pragma unroll
            for (int i = 0; i < 4; i++)
                #pragma unroll
                for (int j = 0; j < 2; j++)
                    wmma::mma_sync(acc[i][j], a[i], bh[j], acc[i][j]);
        }
        __syncthreads();
        s ^= 1;
    }

    /* ---- epilogue via smem (128 x 132 fp32) ---- */
    float* cs = (float*)smem;
    #pragma unroll
    for (int i = 0; i < 4; i++)
        #pragma unroll
        for (int j = 0; j < 2; j++) {
            #pragma unroll
            for (int t = 0; t < acc[i][j].num_elements; t++)
                acc[i][j].x[t] *= alpha;
            wmma::store_matrix_sync(cs + (wm * 64 + i * 16) * 132 + wn * 32 + j * 16,
                                    acc[i][j], 132, wmma::mem_row_major);
        }
    __syncthreads();

    #pragma unroll
    for (int it = 0; it < 16; it++) {
        int idx = it * NT + tid;
        int r = idx >> 5, c4 = (idx & 31) * 4;
        float4 v = *(float4*)(cs + r * 132 + c4);
        if (BIAS) {
            v.x += bias[n0 + c4 + 0];
            v.y += bias[n0 + c4 + 1];
            v.z += bias[n0 + c4 + 2];
            v.w += bias[n0 + c4 + 3];
        }
        size_t base = (size_t)zb * sC + (size_t)(m0 + r) * ldc + n0 + c4;
        if (SPLIT) {
            bf16 h0 = __float2bfloat16(v.x), h1 = __float2bfloat16(v.y);
            bf16 h2 = __float2bfloat16(v.z), h3 = __float2bfloat16(v.w);
            __nv_bfloat162 t;
            t.x = h0; t.y = h1; *(__nv_bfloat162*)(Ch + base) = t;
            t.x = h2; t.y = h3; *(__nv_bfloat162*)(Ch + base + 2) = t;
            t.x = __float2bfloat16(v.x - __bfloat162float(h0));
            t.y = __float2bfloat16(v.y - __bfloat162float(h1));
            *(__nv_bfloat162*)(Cl + base) = t;
            t.x = __float2bfloat16(v.z - __bfloat162float(h2));
            t.y = __float2bfloat16(v.w - __bfloat162float(h3));
            *(__nv_bfloat162*)(Cl + base + 2) = t;
        } else {
            *(float4*)(C + base) = v;
        }
    }
}

/* ---------------- fused input split: x -> xh/xl, ctx -> ch/cl ------------- */
__global__ __launch_bounds__(256) void split_inputs(
    const float* __restrict__ x, const float* __restrict__ ctx,
    bf16* __restrict__ xh, bf16* __restrict__ xl,
    bf16* __restrict__ ch, bf16* __restrict__ cl)
{
    const float* in = blockIdx.y ? ctx : x;
    bf16* h = blockIdx.y ? ch : xh;
    bf16* l = blockIdx.y ? cl : xl;
    size_t i = (size_t)blockIdx.x * 256 + threadIdx.x;
    float4 v = ((const float4*)in)[i];
    bf16 h0 = __float2bfloat16(v.x), h1 = __float2bfloat16(v.y);
    bf16 h2 = __float2bfloat16(v.z), h3 = __float2bfloat16(v.w);
    __nv_bfloat162 t;
    t.x = h0; t.y = h1; *(__nv_bfloat162*)(h + i * 4) = t;
    t.x = h2; t.y = h3; *(__nv_bfloat162*)(h + i * 4 + 2) = t;
    t.x = __float2bfloat16(v.x - __bfloat162float(h0));
    t.y = __float2bfloat16(v.y - __bfloat162float(h1));
    *(__nv_bfloat162*)(l + i * 4) = t;
    t.x = __float2bfloat16(v.z - __bfloat162float(h2));
    t.y = __float2bfloat16(v.w - __bfloat162float(h3));
    *(__nv_bfloat162*)(l + i * 4 + 2) = t;
}

/* ---------------- all weights: W[K,N] -> W^T[N,K] bf16 hi/lo ------------- */
__global__ __launch_bounds__(256) void wsplit_all(
    const float* __restrict__ Wq, const float* __restrict__ Wkv, const float* __restrict__ Wo,
    bf16* __restrict__ qth, bf16* __restrict__ qtl,
    bf16* __restrict__ kvth, bf16* __restrict__ kvtl,
    bf16* __restrict__ oth, bf16* __restrict__ otl)
{
    __shared__ float t[32][33];
    int bx = blockIdx.x;
    const float* W; bf16 *th, *tl; int N, tidx;
    if (bx < 256)      { W = Wq;  th = qth;  tl = qtl;  N = DIM;     tidx = bx; }
    else if (bx < 768) { W = Wkv; th = kvth; tl = kvtl; N = 2 * DIM; tidx = bx - 256; }
    else               { W = Wo;  th = oth;  tl = otl;  N = DIM;     tidx = bx - 768; }
    int nT = N / 32;
    int n0 = (tidx % nT) * 32, k0 = (tidx / nT) * 32;
    int tx = threadIdx.x & 31, ty = threadIdx.x >> 5;
    #pragma unroll
    for (int j = 0; j < 4; j++) {
        int r = ty + j * 8;
        t[r][tx] = W[(size_t)(k0 + r) * N + n0 + tx];
    }
    __syncthreads();
    #pragma unroll
    for (int j = 0; j < 4; j++) {
        int r = ty + j * 8;
        float v = t[tx][r];
        size_t o = (size_t)(n0 + r) * DIM + k0 + tx;
        bf16 h = __float2bfloat16(v);
        th[o] = h;
        tl[o] = __float2bfloat16(v - __bfloat162float(h));
    }
}

/* ---------------- fused attention prep: LN(q)->fp16 hi/lo, LN(k)->fp16,
                    v -> v^T fp16 ---------------- */
__global__ __launch_bounds__(256) void prep_attn(
    const float* __restrict__ q, const float* __restrict__ kv,
    const float* __restrict__ g, const float* __restrict__ b,
    __half* __restrict__ qh, __half* __restrict__ ql,
    __half* __restrict__ kh, __half* __restrict__ vt)
{
    const int mode = blockIdx.y;
    int tid = threadIdx.x;

    if (mode == 2) {                     /* v transpose, fp16 single */
        if (blockIdx.x >= 8192) return;
        __shared__ float t[32][33];
        int bx = blockIdx.x;
        int bb = bx >> 11;               /* /2048 */
        int rem = bx & 2047;
        int d0 = (rem >> 7) * 32;        /* /128 */
        int m0 = (rem & 127) * 32;
        int tx = tid & 31, ty = tid >> 5;
        const float* src = kv + ((size_t)bb * SEQ) * (2 * DIM) + DIM;
        #pragma unroll
        for (int j = 0; j < 4; j++) {
            int r = ty + j * 8;
            t[r][tx] = src[(size_t)(m0 + r) * (2 * DIM) + d0 + tx];
        }
        __syncthreads();
        #pragma unroll
        for (int j = 0; j < 4; j++) {
            int r = ty + j * 8;
            vt[((size_t)bb * DIM + d0 + r) * SEQ + m0 + tx] = __float2half(t[tx][r]);
        }
        return;
    }

    /* LayerNorm over 512 */
    __shared__ float red[16];
    const float* row = (mode == 0) ? q + (size_t)blockIdx.x * DIM
                                   : kv + (size_t)blockIdx.x * (2 * DIM);
    float x0 = row[tid];
    float x1 = row[tid + 256];
    float s  = x0 + x1;
    float sq = x0 * x0 + x1 * x1;
    #pragma unroll
    for (int o = 16; o > 0; o >>= 1) {
        s  += __shfl_xor_sync(0xffffffffu, s,  o);
        sq += __shfl_xor_sync(0xffffffffu, sq, o);
    }
    if ((tid & 31) == 0) { red[tid >> 5] = s; red[8 + (tid >> 5)] = sq; }
    __syncthreads();
    if (tid < 32) {
        float vs = (tid < 8) ? red[tid] : 0.0f;
        float vq = (tid < 8) ? red[8 + tid] : 0.0f;
        #pragma unroll
        for (int o = 4; o > 0; o >>= 1) {
            vs += __shfl_xor_sync(0xffffffffu, vs, o);
            vq += __shfl_xor_sync(0xffffffffu, vq, o);
        }
        if (tid == 0) { red[0] = vs; red[1] = vq; }
    }
    __syncthreads();
    float mean = red[0] * (1.0f / 512.0f);
    float var  = red[1] * (1.0f / 512.0f) - mean * mean;
    float rstd = rsqrtf(var + LN_EPS);
    float y0 = (x0 - mean) * rstd * g[tid]       + b[tid];
    float y1 = (x1 - mean) * rstd * g[tid + 256] + b[tid + 256];
    if (mode == 0) {
        __half* hr = qh + (size_t)blockIdx.x * DIM;
        __half* lr = ql + (size_t)blockIdx.x * DIM;
        __half h0 = __float2half(y0);
        __half h1 = __float2half(y1);
        hr[tid]       = h0;
        hr[tid + 256] = h1;
        lr[tid]       = __float2half(y0 - __half2float(h0));
        lr[tid + 256] = __float2half(y1 - __half2float(h1));
    } else {
        __half* hr = kh + (size_t)blockIdx.x * DIM;
        hr[tid]       = __float2half(y0);
        hr[tid + 256] = __float2half(y1);
    }
}

/* ---------------- softmax(4096) fp32 -> fp16 hi/lo ---------------- */
__global__ __launch_bounds__(256) void softmax_split(
    const float* __restrict__ S, __half* __restrict__ ph, __half* __restrict__ pl)
{
    __shared__ float red[8];
    const float* row = S + (size_t)blockIdx.x * SEQ;
    __half* hr = ph + (size_t)blockIdx.x * SEQ;
    __half* lr = pl + (size_t)blockIdx.x * SEQ;
    int tid = threadIdx.x;
    float v[16];
    float mx = -1e30f;
    #pragma unroll
    for (int i = 0; i < 16; i++) { v[i] = row[tid + i * 256]; mx = fmaxf(mx, v[i]); }
    #pragma unroll
    for (int o = 16; o > 0; o >>= 1) mx = fmaxf(mx, __shfl_xor_sync(0xffffffffu, mx, o));
    if ((tid & 31) == 0) red[tid >> 5] = mx;
    __syncthreads();
    if (tid < 32) {
        float m = (tid < 8) ? red[tid] : -1e30f;
        #pragma unroll
        for (int o = 4; o > 0; o >>= 1) m = fmaxf(m, __shfl_xor_sync(0xffffffffu, m, o));
        if (tid == 0) red[0] = m;
    }
    __syncthreads();
    mx = red[0];
    __syncthreads();
    float s = 0.0f;
    #pragma unroll
    for (int i = 0; i < 16; i++) { v[i] = __expf(v[i] - mx); s += v[i]; }
    #pragma unroll
    for (int o = 16; o > 0; o >>= 1) s += __shfl_xor_sync(0xffffffffu, s, o);
    if ((tid & 31) == 0) red[tid >> 5] = s;
    __syncthreads();
    if (tid < 32) {
        float m = (tid < 8) ? red[tid] : 0.0f;
        #pragma unroll
        for (int o = 4; o > 0; o >>= 1) m += __shfl_xor_sync(0xffffffffu, m, o);
        if (tid == 0) red[0] = m;
    }
    __syncthreads();
    float inv = 1.0f / red[0];
    #pragma unroll
    for (int i = 0; i < 16; i++) {
        float p = v[i] * inv;
        __half h = __float2half(p);
        hr[tid + i * 256] = h;
        lr[tid + i * 256] = __float2half(p - __half2float(h));
    }
}

/* ---------------- launcher ---------------- */
extern "C" void kernel_launch(void* const* d_in, const int* in_sizes, int n_in,
                              void* d_out, int out_size)
{
    const float* x    = (const float*)d_in[0];
    const float* ctx  = (const float*)d_in[1];
    const float* Wq   = (const float*)d_in[2];
    const float* Wkv  = (const float*)d_in[3];
    const float* Wo   = (const float*)d_in[4];
    const float* bo   = (const float*)d_in[5];
    const float* ln_g = (const float*)d_in[6];
    const float* ln_b = (const float*)d_in[7];
    float* out = (float*)d_out;

    float *q, *kv, *S;
    bf16 *xh, *xl, *ch, *cl, *wqth, *wqtl, *wkvth, *wkvtl, *woth, *wotl, *oh, *ol;
    __half *qh, *ql, *kh, *vt, *ph, *pl;
    cudaGetSymbolAddress((void**)&q,    g_q);
    cudaGetSymbolAddress((void**)&kv,   g_kv);
    cudaGetSymbolAddress((void**)&S,    g_S);
    cudaGetSymbolAddress((void**)&xh,   g_xh);    cudaGetSymbolAddress((void**)&xl,   g_xl);
    cudaGetSymbolAddress((void**)&ch,   g_ch);    cudaGetSymbolAddress((void**)&cl,   g_cl);
    cudaGetSymbolAddress((void**)&wqth, g_wqth);  cudaGetSymbolAddress((void**)&wqtl, g_wqtl);
    cudaGetSymbolAddress((void**)&wkvth,g_wkvth); cudaGetSymbolAddress((void**)&wkvtl,g_wkvtl);
    cudaGetSymbolAddress((void**)&woth, g_woth);  cudaGetSymbolAddress((void**)&wotl, g_wotl);
    cudaGetSymbolAddress((void**)&oh,   g_oh);    cudaGetSymbolAddress((void**)&ol,   g_ol);
    cudaGetSymbolAddress((void**)&qh,   g_qh);    cudaGetSymbolAddress((void**)&ql,   g_ql);
    cudaGetSymbolAddress((void**)&kh,   g_kh);    cudaGetSymbolAddress((void**)&vt,   g_vt);
    cudaGetSymbolAddress((void**)&ph,   g_ph);    cudaGetSymbolAddress((void**)&pl,   g_pl);

    cudaFuncSetAttribute(gemm_hilo<bf16,  true,  false, false>,
                         cudaFuncAttributeMaxDynamicSharedMemorySize, SMEM_BYTES);
    cudaFuncSetAttribute(gemm_hilo<bf16,  true,  false, true>,
                         cudaFuncAttributeMaxDynamicSharedMemorySize, SMEM_BYTES);
    cudaFuncSetAttribute(gemm_hilo<__half,false, false, false>,
                         cudaFuncAttributeMaxDynamicSharedMemorySize, SMEM_BYTES);
    cudaFuncSetAttribute(gemm_hilo<__half,false, true,  false>,
                         cudaFuncAttributeMaxDynamicSharedMemorySize, SMEM_BYTES);

    /* 0: split inputs */
    split_inputs<<<dim3(ROWS * DIM / 4 / 256, 2), 256>>>(x, ctx, xh, xl, ch, cl);
    /* 1: split+transpose all weights */
    wsplit_all<<<1024, 256>>>(Wq, Wkv, Wo, wqth, wqtl, wkvth, wkvtl, woth, wotl);

    /* 2: q = x @ Wq (bf16x3) */
    gemm_hilo<bf16,true,false,false><<<dim3(DIM / BN, ROWS / BM, 1), NT, SMEM_BYTES>>>(
        xh, xl, wqth, wqtl, q, nullptr, nullptr, nullptr,
        DIM, DIM, DIM, DIM, 0, 0, 0, 1.0f);

    /* 3: kv = ctx @ Wkv (bf16x3) */
    gemm_hilo<bf16,true,false,false><<<dim3(2 * DIM / BN, ROWS / BM, 1), NT, SMEM_BYTES>>>(
        ch, cl, wkvth, wkvtl, kv, nullptr, nullptr, nullptr,
        DIM, DIM, DIM, 2 * DIM, 0, 0, 0, 1.0f);

    /* 4: LN(q)->fp16 hi/lo, LN(k)->fp16, v->v^T fp16 */
    prep_attn<<<dim3(ROWS, 3), 256>>>(q, kv, ln_g, ln_b, qh, ql, kh, vt);

    /* 5: S = scale * q @ k^T (fp16 x2) — profiled launch */
    gemm_hilo<__half,false,false,false><<<dim3(SEQ / BN, SEQ / BM, BATCH), NT, SMEM_BYTES>>>(
        qh, ql, kh, nullptr, S, nullptr, nullptr, nullptr,
        DIM, DIM, DIM, SEQ,
        (long long)SEQ * DIM, (long long)SEQ * DIM, (long long)SEQ * SEQ, ATTN_SCALE);

    /* 6: P = softmax(S) -> fp16 hi/lo */
    softmax_split<<<BATCH * SEQ, 256>>>(S, ph, pl);

    /* 7: O = P @ v (fp16 x2, split bf16 out) */
    gemm_hilo<__half,false,true,false><<<dim3(DIM / BN, SEQ / BM, BATCH), NT, SMEM_BYTES>>>(
        ph, pl, vt, nullptr, nullptr, oh, ol, nullptr,
        SEQ, SEQ, SEQ, DIM,
        (long long)SEQ * SEQ, (long long)DIM * SEQ, (long long)SEQ * DIM, 1.0f);

    /* 8: out = O @ Wo + bo (bf16x3) */
    gemm_hilo<bf16,true,false,true><<<dim3(DIM / BN, ROWS / BM, 1), NT, SMEM_BYTES>>>(
        oh, ol, woth, wotl, out, nullptr, nullptr, bo,
        DIM, DIM, DIM, DIM, 0, 0, 0, 1.0f);
}

// round 6
// speedup vs baseline: 4.9194x; 1.0452x over previous
#include <cuda_runtime.h>
#include <cuda_bf16.h>
#include <cuda_fp16.h>
#include <mma.h>
#include <cstdint>

using namespace nvcuda;
typedef __nv_bfloat16 bf16;

#define BATCH 4
#define SEQ   4096
#define DIM   512
#define ROWS  16384
#define ATTN_SCALE 0.125f
#define LN_EPS 1e-5f

/* ---------------- scratch (no allocations allowed) ---------------- */
__device__ __align__(256) float g_q [(size_t)ROWS * DIM];
__device__ __align__(256) float g_kv[(size_t)ROWS * 2 * DIM];
__device__ __align__(256) float g_S [(size_t)BATCH * SEQ * SEQ];

__device__ __align__(256) bf16 g_xh [(size_t)ROWS * DIM];
__device__ __align__(256) bf16 g_xl [(size_t)ROWS * DIM];
__device__ __align__(256) bf16 g_ch [(size_t)ROWS * DIM];
__device__ __align__(256) bf16 g_cl [(size_t)ROWS * DIM];
__device__ __align__(256) bf16 g_wqth [DIM * DIM];
__device__ __align__(256) bf16 g_wqtl [DIM * DIM];
__device__ __align__(256) bf16 g_wkvth[2 * DIM * DIM];
__device__ __align__(256) bf16 g_wkvtl[2 * DIM * DIM];
__device__ __align__(256) bf16 g_woth [DIM * DIM];
__device__ __align__(256) bf16 g_wotl [DIM * DIM];
__device__ __align__(256) bf16 g_oh [(size_t)ROWS * DIM];
__device__ __align__(256) bf16 g_ol [(size_t)ROWS * DIM];

__device__ __align__(256) __half g_qh [(size_t)ROWS * DIM];
__device__ __align__(256) __half g_ql [(size_t)ROWS * DIM];
__device__ __align__(256) __half g_kh [(size_t)ROWS * DIM];          /* single */
__device__ __align__(256) __half g_vt [(size_t)BATCH * DIM * SEQ];   /* v^T, single */
__device__ __align__(256) __half g_ph [(size_t)BATCH * SEQ * SEQ];
__device__ __align__(256) __half g_pl [(size_t)BATCH * SEQ * SEQ];

/* ---------------- cp.async helpers ---------------- */
__device__ __forceinline__ unsigned smem_u32(const void* p) {
    return (unsigned)__cvta_generic_to_shared(p);
}
#define CPA16(dst, src) \
    asm volatile("cp.async.cg.shared.global [%0], [%1], 16;\n" :: "r"(dst), "l"(src))
#define CPCOMMIT() asm volatile("cp.async.commit_group;\n" ::)
template<int N> __device__ __forceinline__ void cpwait() {
    asm volatile("cp.async.wait_group %0;\n" :: "n"(N));
}

/* ---------------- hi/lo GEMM ----------------
 * C[M,N] = alpha * (Ah+Al)[M,K] @ B^T  where B is [N,K] row-major.
 * THREE: B = Bh+Bl, 3 MMA passes (drop Al*Bl). !THREE: B single, 2 passes.
 * 128x128 tiles, BKT k-chunk, 256 thr, 8 warps of 64x32, 2-stage cp.async.
 * MMA passes are separated so one accumulator is never hit back-to-back.
 */
#define BM 128
#define BN 128
#define NT  256

template<typename T, int BKT>
__device__ __forceinline__ void stage_tile(unsigned sm, const T* g, int ld, int tid) {
    constexpr int CPR = BKT / 8;            /* 16B chunks per row */
    constexpr int AST = BKT + 8;
    #pragma unroll
    for (int i = 0; i < (128 * CPR) / NT; i++) {
        int idx = i * NT + tid;
        int r = idx / CPR, c = (idx % CPR) * 8;
        CPA16(sm + (unsigned)(r * AST + c) * 2, g + (size_t)r * ld + c);
    }
}

template<typename T, int BKT, bool THREE, bool SPLIT, bool BIAS>
__global__ __launch_bounds__(NT, 2) void gemm_hilo(
    const T* __restrict__ Ah, const T* __restrict__ Al,
    const T* __restrict__ Bh, const T* __restrict__ Bl,
    float* __restrict__ C, bf16* __restrict__ Ch, bf16* __restrict__ Cl,
    const float* __restrict__ bias,
    int K, int lda, int ldb, int ldc,
    long long sA, long long sB, long long sC, float alpha)
{
    extern __shared__ char smem[];
    constexpr int AST = BKT + 8;
    constexpr unsigned TSZ = 128u * AST * 2u;
    constexpr unsigned STG = (THREE ? 4u : 3u) * TSZ;

    const int tid  = threadIdx.x;
    const int warp = tid >> 5;
    const int wm = warp >> 2;
    const int wn = warp & 3;
    const int m0 = blockIdx.y * BM;
    const int n0 = blockIdx.x * BN;
    const long long zb = blockIdx.z;
    const unsigned sb0 = smem_u32(smem);

    const T* gAh = Ah + zb * sA + (size_t)m0 * lda;
    const T* gAl = Al + zb * sA + (size_t)m0 * lda;
    const T* gBh = Bh + zb * sB + (size_t)n0 * ldb;
    const T* gBl = THREE ? (Bl + zb * sB + (size_t)n0 * ldb) : nullptr;

    wmma::fragment<wmma::accumulator, 16, 16, 16, float> acc[4][2];
    #pragma unroll
    for (int i = 0; i < 4; i++)
        #pragma unroll
        for (int j = 0; j < 2; j++)
            wmma::fill_fragment(acc[i][j], 0.0f);

    auto stage = [&](int s, int k0) {
        unsigned sp = sb0 + (unsigned)s * STG;
        stage_tile<T, BKT>(sp,            gAh + k0, lda, tid);
        stage_tile<T, BKT>(sp + TSZ,      gAl + k0, lda, tid);
        stage_tile<T, BKT>(sp + 2u * TSZ, gBh + k0, ldb, tid);
        if (THREE) stage_tile<T, BKT>(sp + 3u * TSZ, gBl + k0, ldb, tid);
        CPCOMMIT();
    };

    stage(0, 0);
    int s = 0;
    for (int k0 = 0; k0 < K; k0 += BKT) {
        if (k0 + BKT < K) { stage(s ^ 1, k0 + BKT); cpwait<1>(); }
        else              { cpwait<0>(); }
        __syncthreads();

        T* sAh = (T*)(smem + s * STG);
        T* sAl = (T*)(smem + s * STG + TSZ);
        T* sBh = (T*)(smem + s * STG + 2 * TSZ);
        T* sBl = (T*)(smem + s * STG + 3 * TSZ);

        #pragma unroll
        for (int kk = 0; kk < BKT; kk += 16) {
            wmma::fragment<wmma::matrix_a, 16, 16, 16, T, wmma::row_major> a[4];
            wmma::fragment<wmma::matrix_b, 16, 16, 16, T, wmma::col_major> bh[2];
            #pragma unroll
            for (int i = 0; i < 4; i++)
                wmma::load_matrix_sync(a[i], sAh + (wm * 64 + i * 16) * AST + kk, AST);
            #pragma unroll
            for (int j = 0; j < 2; j++)
                wmma::load_matrix_sync(bh[j], sBh + (wn * 32 + j * 16) * AST + kk, AST);

            /* pass 1: Ah x Bh (8 distinct accumulators) */
            #pragma unroll
            for (int i = 0; i < 4; i++)
                #pragma unroll
                for (int j = 0; j < 2; j++)
                    wmma::mma_sync(acc[i][j], a[i], bh[j], acc[i][j]);

            if (THREE) {
                /* pass 2: Ah x Bl */
                wmma::fragment<wmma::matrix_b, 16, 16, 16, T, wmma::col_major> bl[2];
                #pragma unroll
                for (int j = 0; j < 2; j++)
                    wmma::load_matrix_sync(bl[j], sBl + (wn * 32 + j * 16) * AST + kk, AST);
                #pragma unroll
                for (int i = 0; i < 4; i++)
                    #pragma unroll
                    for (int j = 0; j < 2; j++)
                        wmma::mma_sync(acc[i][j], a[i], bl[j], acc[i][j]);
            }

            /* pass 3 (or 2): Al x Bh */
            #pragma unroll
            for (int i = 0; i < 4; i++)
                wmma::load_matrix_sync(a[i], sAl + (wm * 64 + i * 16) * AST + kk, AST);
            #pragma unroll
            for (int i = 0; i < 4; i++)
                #pragma unroll
                for (int j = 0; j < 2; j++)
                    wmma::mma_sync(acc[i][j], a[i], bh[j], acc[i][j]);
        }
        __syncthreads();
        s ^= 1;
    }

    /* ---- epilogue via smem (128 x 132 fp32) ---- */
    float* cs = (float*)smem;
    #pragma unroll
    for (int i = 0; i < 4; i++)
        #pragma unroll
        for (int j = 0; j < 2; j++) {
            #pragma unroll
            for (int t = 0; t < acc[i][j].num_elements; t++)
                acc[i][j].x[t] *= alpha;
            wmma::store_matrix_sync(cs + (wm * 64 + i * 16) * 132 + wn * 32 + j * 16,
                                    acc[i][j], 132, wmma::mem_row_major);
        }
    __syncthreads();

    #pragma unroll
    for (int it = 0; it < 16; it++) {
        int idx = it * NT + tid;
        int r = idx >> 5, c4 = (idx & 31) * 4;
        float4 v = *(float4*)(cs + r * 132 + c4);
        if (BIAS) {
            v.x += bias[n0 + c4 + 0];
            v.y += bias[n0 + c4 + 1];
            v.z += bias[n0 + c4 + 2];
            v.w += bias[n0 + c4 + 3];
        }
        size_t base = (size_t)zb * sC + (size_t)(m0 + r) * ldc + n0 + c4;
        if (SPLIT) {
            bf16 h0 = __float2bfloat16(v.x), h1 = __float2bfloat16(v.y);
            bf16 h2 = __float2bfloat16(v.z), h3 = __float2bfloat16(v.w);
            __nv_bfloat162 t;
            t.x = h0; t.y = h1; *(__nv_bfloat162*)(Ch + base) = t;
            t.x = h2; t.y = h3; *(__nv_bfloat162*)(Ch + base + 2) = t;
            t.x = __float2bfloat16(v.x - __bfloat162float(h0));
            t.y = __float2bfloat16(v.y - __bfloat162float(h1));
            *(__nv_bfloat162*)(Cl + base) = t;
            t.x = __float2bfloat16(v.z - __bfloat162float(h2));
            t.y = __float2bfloat16(v.w - __bfloat162float(h3));
            *(__nv_bfloat162*)(Cl + base + 2) = t;
        } else {
            *(float4*)(C + base) = v;
        }
    }
}

/* ---------------- fused input split: x -> xh/xl, ctx -> ch/cl ------------- */
__global__ __launch_bounds__(256) void split_inputs(
    const float* __restrict__ x, const float* __restrict__ ctx,
    bf16* __restrict__ xh, bf16* __restrict__ xl,
    bf16* __restrict__ ch, bf16* __restrict__ cl)
{
    const float* in = blockIdx.y ? ctx : x;
    bf16* h = blockIdx.y ? ch : xh;
    bf16* l = blockIdx.y ? cl : xl;
    size_t i = (size_t)blockIdx.x * 256 + threadIdx.x;
    float4 v = ((const float4*)in)[i];
    bf16 h0 = __float2bfloat16(v.x), h1 = __float2bfloat16(v.y);
    bf16 h2 = __float2bfloat16(v.z), h3 = __float2bfloat16(v.w);
    __nv_bfloat162 t;
    t.x = h0; t.y = h1; *(__nv_bfloat162*)(h + i * 4) = t;
    t.x = h2; t.y = h3; *(__nv_bfloat162*)(h + i * 4 + 2) = t;
    t.x = __float2bfloat16(v.x - __bfloat162float(h0));
    t.y = __float2bfloat16(v.y - __bfloat162float(h1));
    *(__nv_bfloat162*)(l + i * 4) = t;
    t.x = __float2bfloat16(v.z - __bfloat162float(h2));
    t.y = __float2bfloat16(v.w - __bfloat162float(h3));
    *(__nv_bfloat162*)(l + i * 4 + 2) = t;
}

/* ---------------- all weights: W[K,N] -> W^T[N,K] bf16 hi/lo ------------- */
__global__ __launch_bounds__(256) void wsplit_all(
    const float* __restrict__ Wq, const float* __restrict__ Wkv, const float* __restrict__ Wo,
    bf16* __restrict__ qth, bf16* __restrict__ qtl,
    bf16* __restrict__ kvth, bf16* __restrict__ kvtl,
    bf16* __restrict__ oth, bf16* __restrict__ otl)
{
    __shared__ float t[32][33];
    int bx = blockIdx.x;
    const float* W; bf16 *th, *tl; int N, tidx;
    if (bx < 256)      { W = Wq;  th = qth;  tl = qtl;  N = DIM;     tidx = bx; }
    else if (bx < 768) { W = Wkv; th = kvth; tl = kvtl; N = 2 * DIM; tidx = bx - 256; }
    else               { W = Wo;  th = oth;  tl = otl;  N = DIM;     tidx = bx - 768; }
    int nT = N / 32;
    int n0 = (tidx % nT) * 32, k0 = (tidx / nT) * 32;
    int tx = threadIdx.x & 31, ty = threadIdx.x >> 5;
    #pragma unroll
    for (int j = 0; j < 4; j++) {
        int r = ty + j * 8;
        t[r][tx] = W[(size_t)(k0 + r) * N + n0 + tx];
    }
    __syncthreads();
    #pragma unroll
    for (int j = 0; j < 4; j++) {
        int r = ty + j * 8;
        float v = t[tx][r];
        size_t o = (size_t)(n0 + r) * DIM + k0 + tx;
        bf16 h = __float2bfloat16(v);
        th[o] = h;
        tl[o] = __float2bfloat16(v - __bfloat162float(h));
    }
}

/* ---------------- fused attention prep ---------------- */
__global__ __launch_bounds__(256) void prep_attn(
    const float* __restrict__ q, const float* __restrict__ kv,
    const float* __restrict__ g, const float* __restrict__ b,
    __half* __restrict__ qh, __half* __restrict__ ql,
    __half* __restrict__ kh, __half* __restrict__ vt)
{
    const int mode = blockIdx.y;
    int tid = threadIdx.x;

    if (mode == 2) {                     /* v transpose, fp16 single */
        if (blockIdx.x >= 8192) return;
        __shared__ float t[32][33];
        int bx = blockIdx.x;
        int bb = bx >> 11;
        int rem = bx & 2047;
        int d0 = (rem >> 7) * 32;
        int m0 = (rem & 127) * 32;
        int tx = tid & 31, ty = tid >> 5;
        const float* src = kv + ((size_t)bb * SEQ) * (2 * DIM) + DIM;
        #pragma unroll
        for (int j = 0; j < 4; j++) {
            int r = ty + j * 8;
            t[r][tx] = src[(size_t)(m0 + r) * (2 * DIM) + d0 + tx];
        }
        __syncthreads();
        #pragma unroll
        for (int j = 0; j < 4; j++) {
            int r = ty + j * 8;
            vt[((size_t)bb * DIM + d0 + r) * SEQ + m0 + tx] = __float2half(t[tx][r]);
        }
        return;
    }

    __shared__ float red[16];
    const float* row = (mode == 0) ? q + (size_t)blockIdx.x * DIM
                                   : kv + (size_t)blockIdx.x * (2 * DIM);
    float x0 = row[tid];
    float x1 = row[tid + 256];
    float s  = x0 + x1;
    float sq = x0 * x0 + x1 * x1;
    #pragma unroll
    for (int o = 16; o > 0; o >>= 1) {
        s  += __shfl_xor_sync(0xffffffffu, s,  o);
        sq += __shfl_xor_sync(0xffffffffu, sq, o);
    }
    if ((tid & 31) == 0) { red[tid >> 5] = s; red[8 + (tid >> 5)] = sq; }
    __syncthreads();
    if (tid < 32) {
        float vs = (tid < 8) ? red[tid] : 0.0f;
        float vq = (tid < 8) ? red[8 + tid] : 0.0f;
        #pragma unroll
        for (int o = 4; o > 0; o >>= 1) {
            vs += __shfl_xor_sync(0xffffffffu, vs, o);
            vq += __shfl_xor_sync(0xffffffffu, vq, o);
        }
        if (tid == 0) { red[0] = vs; red[1] = vq; }
    }
    __syncthreads();
    float mean = red[0] * (1.0f / 512.0f);
    float var  = red[1] * (1.0f / 512.0f) - mean * mean;
    float rstd = rsqrtf(var + LN_EPS);
    float y0 = (x0 - mean) * rstd * g[tid]       + b[tid];
    float y1 = (x1 - mean) * rstd * g[tid + 256] + b[tid + 256];
    if (mode == 0) {
        __half* hr = qh + (size_t)blockIdx.x * DIM;
        __half* lr = ql + (size_t)blockIdx.x * DIM;
        __half h0 = __float2half(y0);
        __half h1 = __float2half(y1);
        hr[tid]       = h0;
        hr[tid + 256] = h1;
        lr[tid]       = __float2half(y0 - __half2float(h0));
        lr[tid + 256] = __float2half(y1 - __half2float(h1));
    } else {
        __half* hr = kh + (size_t)blockIdx.x * DIM;
        hr[tid]       = __float2half(y0);
        hr[tid + 256] = __float2half(y1);
    }
}

/* ---------------- softmax(4096) fp32 -> fp16 hi/lo ---------------- */
__global__ __launch_bounds__(256) void softmax_split(
    const float* __restrict__ S, __half* __restrict__ ph, __half* __restrict__ pl)
{
    __shared__ float red[8];
    const float* row = S + (size_t)blockIdx.x * SEQ;
    __half* hr = ph + (size_t)blockIdx.x * SEQ;
    __half* lr = pl + (size_t)blockIdx.x * SEQ;
    int tid = threadIdx.x;
    float v[16];
    float mx = -1e30f;
    #pragma unroll
    for (int i = 0; i < 16; i++) { v[i] = row[tid + i * 256]; mx = fmaxf(mx, v[i]); }
    #pragma unroll
    for (int o = 16; o > 0; o >>= 1) mx = fmaxf(mx, __shfl_xor_sync(0xffffffffu, mx, o));
    if ((tid & 31) == 0) red[tid >> 5] = mx;
    __syncthreads();
    if (tid < 32) {
        float m = (tid < 8) ? red[tid] : -1e30f;
        #pragma unroll
        for (int o = 4; o > 0; o >>= 1) m = fmaxf(m, __shfl_xor_sync(0xffffffffu, m, o));
        if (tid == 0) red[0] = m;
    }
    __syncthreads();
    mx = red[0];
    __syncthreads();
    float s = 0.0f;
    #pragma unroll
    for (int i = 0; i < 16; i++) { v[i] = __expf(v[i] - mx); s += v[i]; }
    #pragma unroll
    for (int o = 16; o > 0; o >>= 1) s += __shfl_xor_sync(0xffffffffu, s, o);
    if ((tid & 31) == 0) red[tid >> 5] = s;
    __syncthreads();
    if (tid < 32) {
        float m = (tid < 8) ? red[tid] : 0.0f;
        #pragma unroll
        for (int o = 4; o > 0; o >>= 1) m += __shfl_xor_sync(0xffffffffu, m, o);
        if (tid == 0) red[0] = m;
    }
    __syncthreads();
    float inv = 1.0f / red[0];
    #pragma unroll
    for (int i = 0; i < 16; i++) {
        float p = v[i] * inv;
        __half h = __float2half(p);
        hr[tid + i * 256] = h;
        lr[tid + i * 256] = __float2half(p - __half2float(h));
    }
}

/* ---------------- launcher ---------------- */
#define SMEM_P 81920u      /* projections: 2 stages x 4 tiles (BK=32)   */
#define SMEM_A 110592u     /* attention:  2 stages x 3 tiles (BK=64)    */

extern "C" void kernel_launch(void* const* d_in, const int* in_sizes, int n_in,
                              void* d_out, int out_size)
{
    const float* x    = (const float*)d_in[0];
    const float* ctx  = (const float*)d_in[1];
    const float* Wq   = (const float*)d_in[2];
    const float* Wkv  = (const float*)d_in[3];
    const float* Wo   = (const float*)d_in[4];
    const float* bo   = (const float*)d_in[5];
    const float* ln_g = (const float*)d_in[6];
    const float* ln_b = (const float*)d_in[7];
    float* out = (float*)d_out;

    float *q, *kv, *S;
    bf16 *xh, *xl, *ch, *cl, *wqth, *wqtl, *wkvth, *wkvtl, *woth, *wotl, *oh, *ol;
    __half *qh, *ql, *kh, *vt, *ph, *pl;
    cudaGetSymbolAddress((void**)&q,    g_q);
    cudaGetSymbolAddress((void**)&kv,   g_kv);
    cudaGetSymbolAddress((void**)&S,    g_S);
    cudaGetSymbolAddress((void**)&xh,   g_xh);    cudaGetSymbolAddress((void**)&xl,   g_xl);
    cudaGetSymbolAddress((void**)&ch,   g_ch);    cudaGetSymbolAddress((void**)&cl,   g_cl);
    cudaGetSymbolAddress((void**)&wqth, g_wqth);  cudaGetSymbolAddress((void**)&wqtl, g_wqtl);
    cudaGetSymbolAddress((void**)&wkvth,g_wkvth); cudaGetSymbolAddress((void**)&wkvtl,g_wkvtl);
    cudaGetSymbolAddress((void**)&woth, g_woth);  cudaGetSymbolAddress((void**)&wotl, g_wotl);
    cudaGetSymbolAddress((void**)&oh,   g_oh);    cudaGetSymbolAddress((void**)&ol,   g_ol);
    cudaGetSymbolAddress((void**)&qh,   g_qh);    cudaGetSymbolAddress((void**)&ql,   g_ql);
    cudaGetSymbolAddress((void**)&kh,   g_kh);    cudaGetSymbolAddress((void**)&vt,   g_vt);
    cudaGetSymbolAddress((void**)&ph,   g_ph);    cudaGetSymbolAddress((void**)&pl,   g_pl);

    cudaFuncSetAttribute(gemm_hilo<bf16,  32, true,  false, false>,
                         cudaFuncAttributeMaxDynamicSharedMemorySize, SMEM_P);
    cudaFuncSetAttribute(gemm_hilo<bf16,  32, true,  false, true>,
                         cudaFuncAttributeMaxDynamicSharedMemorySize, SMEM_P);
    cudaFuncSetAttribute(gemm_hilo<__half,64, false, false, false>,
                         cudaFuncAttributeMaxDynamicSharedMemorySize, SMEM_A);
    cudaFuncSetAttribute(gemm_hilo<__half,64, false, true,  false>,
                         cudaFuncAttributeMaxDynamicSharedMemorySize, SMEM_A);

    /* 0: split inputs */
    split_inputs<<<dim3(ROWS * DIM / 4 / 256, 2), 256>>>(x, ctx, xh, xl, ch, cl);
    /* 1: split+transpose all weights */
    wsplit_all<<<1024, 256>>>(Wq, Wkv, Wo, wqth, wqtl, wkvth, wkvtl, woth, wotl);

    /* 2: q = x @ Wq (bf16x3, BK=32) */
    gemm_hilo<bf16,32,true,false,false><<<dim3(DIM / BN, ROWS / BM, 1), NT, SMEM_P>>>(
        xh, xl, wqth, wqtl, q, nullptr, nullptr, nullptr,
        DIM, DIM, DIM, DIM, 0, 0, 0, 1.0f);

    /* 3: kv = ctx @ Wkv (bf16x3, BK=32) */
    gemm_hilo<bf16,32,true,false,false><<<dim3(2 * DIM / BN, ROWS / BM, 1), NT, SMEM_P>>>(
        ch, cl, wkvth, wkvtl, kv, nullptr, nullptr, nullptr,
        DIM, DIM, DIM, 2 * DIM, 0, 0, 0, 1.0f);

    /* 4: LN(q)->fp16 hi/lo, LN(k)->fp16, v->v^T fp16 */
    prep_attn<<<dim3(ROWS, 3), 256>>>(q, kv, ln_g, ln_b, qh, ql, kh, vt);

    /* 5: S = scale * q @ k^T (fp16 x2, BK=64) */
    gemm_hilo<__half,64,false,false,false><<<dim3(SEQ / BN, SEQ / BM, BATCH), NT, SMEM_A>>>(
        qh, ql, kh, nullptr, S, nullptr, nullptr, nullptr,
        DIM, DIM, DIM, SEQ,
        (long long)SEQ * DIM, (long long)SEQ * DIM, (long long)SEQ * SEQ, ATTN_SCALE);

    /* 6: P = softmax(S) -> fp16 hi/lo */
    softmax_split<<<BATCH * SEQ, 256>>>(S, ph, pl);

    /* 7: O = P @ v (fp16 x2, BK=64, split bf16 out) */
    gemm_hilo<__half,64,false,true,false><<<dim3(DIM / BN, SEQ / BM, BATCH), NT, SMEM_A>>>(
        ph, pl, vt, nullptr, nullptr, oh, ol, nullptr,
        SEQ, SEQ, SEQ, DIM,
        (long long)SEQ * SEQ, (long long)DIM * SEQ, (long long)SEQ * DIM, 1.0f);

    /* 8: out = O @ Wo + bo (bf16x3, BK=32) */
    gemm_hilo<bf16,32,true,false,true><<<dim3(DIM / BN, ROWS / BM, 1), NT, SMEM_P>>>(
        oh, ol, woth, wotl, out, nullptr, nullptr, bo,
        DIM, DIM, DIM, DIM, 0, 0, 0, 1.0f);
}